// round 1
// baseline (speedup 1.0000x reference)
#include <cuda_runtime.h>
#include <math.h>

#define LT   4
#define BB   8
#define LL   1024
#define DIM  256
#define NROWS (LT*BB*LL)     // 32768
#define HEADS 8
#define HD    32
#define RS    64
#define RR    16              // regions = LL/RS
#define NTOPK 4
#define QKVC  768
#define HID   1024

// ---------------- scratch (device globals; no allocations allowed) ----------
__device__ float g_spk [NROWS*DIM];      // spikes s1 / s2 (reused)
__device__ float g_qkv [NROWS*QKVC];     // q|k|v
__device__ float g_qr  [LT*BB*RR*DIM];
__device__ float g_kr  [LT*BB*RR*DIM];
__device__ int   g_idx [LT*BB*RR*NTOPK];
__device__ float g_attn[NROWS*DIM];
__device__ float g_x1  [NROWS*DIM];
__device__ float g_h   [NROWS*HID];
__device__ float g_psum[128*DIM];
__device__ float g_psq [128*DIM];
__device__ float g_mean[DIM];
__device__ float g_var [DIM];

// ---------------- batchnorm stats (deterministic 2-stage) -------------------
__global__ void stats1(const float* __restrict__ in) {
    int blk = blockIdx.x, d = threadIdx.x;       // 128 blocks x 256 thr
    float s = 0.f, sq = 0.f;
    int r0 = blk * 256;
    for (int i = 0; i < 256; i++) {
        float v = in[(size_t)(r0 + i) * DIM + d];
        s += v; sq += v * v;
    }
    g_psum[blk*DIM + d] = s;
    g_psq [blk*DIM + d] = sq;
}

__global__ void stats2() {
    int d = threadIdx.x;
    float s = 0.f, sq = 0.f;
    for (int b = 0; b < 128; b++) { s += g_psum[b*DIM+d]; sq += g_psq[b*DIM+d]; }
    float mu = s / (float)NROWS;
    float var = sq / (float)NROWS - mu * mu;
    g_mean[d] = mu;
    g_var[d]  = var > 0.f ? var : 0.f;
}

// ---------------- batchnorm apply + LIF over time -> spikes -----------------
__global__ void bnlif(const float* __restrict__ in,
                      const float* __restrict__ gamma,
                      const float* __restrict__ beta) {
    int tid = blockIdx.x * 256 + threadIdx.x;    // over (b,l,d) = 2M
    int d = tid & 255;
    float mu = g_mean[d];
    float iv = 1.0f / sqrtf(g_var[d] + 1e-5f);
    float ga = gamma[d], be = beta[d];
    const size_t stride = (size_t)BB * LL * DIM;
    size_t base = (size_t)tid;
    float v = 0.f;
    #pragma unroll
    for (int t = 0; t < LT; t++) {
        float xt = (in[base + t*stride] - mu) * iv * ga + be;
        v += (xt - v) * 0.5f;                    // TAU = 2
        float sp;
        if (v >= 1.0f) { sp = 1.f; v = 0.f; } else sp = 0.f;
        g_spk[base + t*stride] = sp;
    }
}

// ---------------- sparse (binary-activation) GEMM: out = spk @ W + b --------
template <int C, bool GELU>
__global__ void spgemm(const float* __restrict__ W,
                       const float* __restrict__ bias,
                       float* __restrict__ out) {
    int n = blockIdx.x, tid = threadIdx.x;
    __shared__ int list[256];
    __shared__ unsigned masks[8];
    __shared__ int offs[9];
    float sv = g_spk[(size_t)n * DIM + tid];
    unsigned m = __ballot_sync(0xffffffffu, sv > 0.5f);
    int warp = tid >> 5, lane = tid & 31;
    if (lane == 0) masks[warp] = m;
    __syncthreads();
    if (tid == 0) {
        int o = 0;
        #pragma unroll
        for (int w = 0; w < 8; w++) { offs[w] = o; o += __popc(masks[w]); }
        offs[8] = o;
    }
    __syncthreads();
    if (sv > 0.5f)
        list[offs[warp] + __popc(m & ((1u << lane) - 1u))] = tid;
    int cnt = offs[8];
    __syncthreads();

    const int ncols = C * 256;
    float acc[C];
    #pragma unroll
    for (int c = 0; c < C; c++) acc[c] = bias[c*256 + tid];
    for (int i = 0; i < cnt; i++) {
        const float* wr = W + (size_t)list[i] * ncols;
        #pragma unroll
        for (int c = 0; c < C; c++) acc[c] += wr[c*256 + tid];
    }
    if (GELU) {
        #pragma unroll
        for (int c = 0; c < C; c++) {
            float x = acc[c];
            acc[c] = 0.5f * x * (1.f + erff(x * 0.70710678118654752f));
        }
    }
    float* op = out + (size_t)n * ncols;
    #pragma unroll
    for (int c = 0; c < C; c++) op[c*256 + tid] = acc[c];
}

// ---------------- region means of q,k ---------------------------------------
__global__ void regmean() {                      // 512 blocks x 256 thr
    int blk = blockIdx.x, d = threadIdx.x;
    int n0 = (blk >> 4) * LL + (blk & 15) * RS;
    float sq = 0.f, sk = 0.f;
    for (int i = 0; i < RS; i++) {
        const float* p = g_qkv + (size_t)(n0 + i) * QKVC + d;
        sq += p[0];
        sk += p[DIM];
    }
    g_qr[blk*DIM + d] = sq * (1.f/RS);
    g_kr[blk*DIM + d] = sk * (1.f/RS);
}

// ---------------- region affinity + top-k -----------------------------------
__global__ void afftopk() {                      // 32 blocks x 256 thr
    __shared__ float qs[16][257];
    __shared__ float ks[16][257];
    __shared__ float aff[16][17];
    int tb = blockIdx.x, tid = threadIdx.x;
    for (int idx = tid; idx < 16*256; idx += 256) {
        int rr = idx >> 8, d = idx & 255;
        qs[rr][d] = g_qr[(tb*16 + rr)*DIM + d];
        ks[rr][d] = g_kr[(tb*16 + rr)*DIM + d];
    }
    __syncthreads();
    int r = tid >> 4, s = tid & 15;
    float a = 0.f;
    #pragma unroll 8
    for (int d = 0; d < 256; d++) a += qs[r][d] * ks[s][d];
    aff[r][s] = a;
    __syncthreads();
    if (tid < 16) {
        float vals[16];
        #pragma unroll
        for (int s2 = 0; s2 < 16; s2++) vals[s2] = aff[tid][s2];
        #pragma unroll
        for (int m = 0; m < NTOPK; m++) {
            int best = 0; float bv = vals[0];
            #pragma unroll
            for (int s2 = 1; s2 < 16; s2++)
                if (vals[s2] > bv) { bv = vals[s2]; best = s2; }
            g_idx[(tb*16 + tid)*NTOPK + m] = best;
            vals[best] = -1e30f;
        }
    }
}

// ---------------- bi-level attention (per t,b,region,head) ------------------
__global__ void attn_kernel() {                  // 4096 blocks x 64 thr
    int bid = blockIdx.x;
    int h  = bid & 7;
    int r  = (bid >> 3) & 15;
    int tb = bid >> 7;
    int i  = threadIdx.x;
    int nq = tb * LL + r * RS + i;
    const float* qp = g_qkv + (size_t)nq * QKVC + h * HD;
    float4 q4[8];
    #pragma unroll
    for (int d = 0; d < 8; d++) q4[d] = *(const float4*)(qp + d*4);
    float4 o4[8];
    #pragma unroll
    for (int d = 0; d < 8; d++) o4[d] = make_float4(0.f,0.f,0.f,0.f);
    float lsum = 0.f;
    __shared__ float4 Ks[64*8];
    __shared__ float4 Vs[64*8];
    const float sc_hd = 0.17677669529663687f;    // 1/sqrt(32)
    for (int reg = 0; reg < NTOPK; reg++) {
        int s = g_idx[(tb*RR + r)*NTOPK + reg];
        int nk = tb * LL + s * RS + i;
        const float* kp = g_qkv + (size_t)nk * QKVC + DIM + h * HD;
        const float* vp = kp + DIM;
        #pragma unroll
        for (int d = 0; d < 8; d++) {
            Ks[i*8 + d] = *(const float4*)(kp + d*4);
            Vs[i*8 + d] = *(const float4*)(vp + d*4);
        }
        __syncthreads();
        for (int j = 0; j < 64; j++) {
            float sc = 0.f;
            #pragma unroll
            for (int d = 0; d < 8; d++) {
                float4 kk = Ks[j*8 + d];
                sc += q4[d].x*kk.x + q4[d].y*kk.y + q4[d].z*kk.z + q4[d].w*kk.w;
            }
            float e = __expf(sc * sc_hd);
            lsum += e;
            #pragma unroll
            for (int d = 0; d < 8; d++) {
                float4 vv = Vs[j*8 + d];
                o4[d].x += e*vv.x; o4[d].y += e*vv.y;
                o4[d].z += e*vv.z; o4[d].w += e*vv.w;
            }
        }
        __syncthreads();
    }
    float inv = 1.f / lsum;
    float* op = g_attn + (size_t)nq * DIM + h * HD;
    #pragma unroll
    for (int d = 0; d < 8; d++) {
        float4 o = o4[d];
        o.x *= inv; o.y *= inv; o.z *= inv; o.w *= inv;
        *(float4*)(op + d*4) = o;
    }
}

// ---------------- dense SGEMM with residual epilogue ------------------------
// out = res + scale * (A @ Bw + bias)
__global__ void sgemm_res(const float* __restrict__ A,
                          const float* __restrict__ Bw,
                          const float* __restrict__ bias,
                          const float* __restrict__ res,
                          const float* __restrict__ scale_p,
                          float* __restrict__ out,
                          int M, int N, int K) {
    __shared__ float As[8][128];
    __shared__ float Bs[8][128];
    int tid = threadIdx.x;
    int row0 = blockIdx.y * 128, col0 = blockIdx.x * 128;
    int lr = tid >> 1;
    int lk = (tid & 1) * 4;
    int bk = tid >> 5;
    int bc = (tid & 31) * 4;
    int tx = tid & 15, ty = tid >> 4;
    float acc[8][8];
    #pragma unroll
    for (int i = 0; i < 8; i++)
        #pragma unroll
        for (int j = 0; j < 8; j++) acc[i][j] = 0.f;

    for (int k0 = 0; k0 < K; k0 += 8) {
        float4 a = *(const float4*)(A + (size_t)(row0 + lr)*K + k0 + lk);
        As[lk+0][lr] = a.x; As[lk+1][lr] = a.y;
        As[lk+2][lr] = a.z; As[lk+3][lr] = a.w;
        float4 b = *(const float4*)(Bw + (size_t)(k0 + bk)*N + col0 + bc);
        *(float4*)&Bs[bk][bc] = b;
        __syncthreads();
        #pragma unroll
        for (int kk = 0; kk < 8; kk++) {
            float ar[8], br[8];
            #pragma unroll
            for (int i = 0; i < 8; i++) ar[i] = As[kk][ty*8 + i];
            #pragma unroll
            for (int j = 0; j < 8; j++) br[j] = Bs[kk][tx*8 + j];
            #pragma unroll
            for (int i = 0; i < 8; i++)
                #pragma unroll
                for (int j = 0; j < 8; j++) acc[i][j] += ar[i]*br[j];
        }
        __syncthreads();
    }
    float sc = *scale_p;
    float4 bv0 = *(const float4*)(bias + col0 + tx*8);
    float4 bv1 = *(const float4*)(bias + col0 + tx*8 + 4);
    #pragma unroll
    for (int i = 0; i < 8; i++) {
        size_t ro = (size_t)(row0 + ty*8 + i)*N + col0 + tx*8;
        float4 r0v = *(const float4*)(res + ro);
        float4 r1v = *(const float4*)(res + ro + 4);
        float4 o0, o1;
        o0.x = r0v.x + sc*(acc[i][0] + bv0.x);
        o0.y = r0v.y + sc*(acc[i][1] + bv0.y);
        o0.z = r0v.z + sc*(acc[i][2] + bv0.z);
        o0.w = r0v.w + sc*(acc[i][3] + bv0.w);
        o1.x = r1v.x + sc*(acc[i][4] + bv1.x);
        o1.y = r1v.y + sc*(acc[i][5] + bv1.y);
        o1.z = r1v.z + sc*(acc[i][6] + bv1.z);
        o1.w = r1v.w + sc*(acc[i][7] + bv1.w);
        *(float4*)(out + ro)     = o0;
        *(float4*)(out + ro + 4) = o1;
    }
}

// ---------------- launch -----------------------------------------------------
extern "C" void kernel_launch(void* const* d_in, const int* in_sizes, int n_in,
                              void* d_out, int out_size) {
    const float* x     = (const float*)d_in[0];
    const float* bn1_g = (const float*)d_in[1];
    const float* bn1_b = (const float*)d_in[2];
    const float* Wqkv  = (const float*)d_in[3];
    const float* bqkv  = (const float*)d_in[4];
    const float* Wo    = (const float*)d_in[5];
    const float* bo    = (const float*)d_in[6];
    const float* bn2_g = (const float*)d_in[7];
    const float* bn2_b = (const float*)d_in[8];
    const float* W1    = (const float*)d_in[9];
    const float* b1    = (const float*)d_in[10];
    const float* W2    = (const float*)d_in[11];
    const float* b2    = (const float*)d_in[12];
    const float* scale = (const float*)d_in[13];
    float* out = (float*)d_out;

    float *p_x1, *p_attn, *p_h, *p_qkv;
    cudaGetSymbolAddress((void**)&p_x1,   g_x1);
    cudaGetSymbolAddress((void**)&p_attn, g_attn);
    cudaGetSymbolAddress((void**)&p_h,    g_h);
    cudaGetSymbolAddress((void**)&p_qkv,  g_qkv);

    // stage 1: bn1 + LIF -> s1
    stats1<<<128, 256>>>(x);
    stats2<<<1, 256>>>();
    bnlif<<<(BB*LL*DIM)/256, 256>>>(x, bn1_g, bn1_b);

    // qkv = s1 @ Wqkv + bqkv (sparse binary gather)
    spgemm<3, false><<<NROWS, 256>>>(Wqkv, bqkv, p_qkv);

    // region means, affinity, top-k, attention
    regmean<<<512, 256>>>();
    afftopk<<<32, 256>>>();
    attn_kernel<<<LT*BB*RR*HEADS, 64>>>();

    // x1 = x + scale * (attn @ Wo + bo)
    dim3 g7(DIM/128, NROWS/128);
    sgemm_res<<<g7, 256>>>(p_attn, Wo, bo, x, scale, p_x1, NROWS, DIM, DIM);

    // stage 2: bn2 + LIF -> s2
    stats1<<<128, 256>>>(p_x1);
    stats2<<<1, 256>>>();
    bnlif<<<(BB*LL*DIM)/256, 256>>>(p_x1, bn2_g, bn2_b);

    // h = gelu(s2 @ W1 + b1) (sparse binary gather)
    spgemm<4, true><<<NROWS, 256>>>(W1, b1, p_h);

    // out = x1 + scale * (h @ W2 + b2)
    sgemm_res<<<g7, 256>>>(p_h, W2, b2, p_x1, scale, out, NROWS, DIM, HID);
}

// round 2
// speedup vs baseline: 1.4715x; 1.4715x over previous
#include <cuda_runtime.h>
#include <math.h>
#include <stdint.h>

#define LT   4
#define BB   8
#define LL   1024
#define DIM  256
#define NROWS (LT*BB*LL)     // 32768
#define HEADS 8
#define HD    32
#define RS    64
#define RR    16              // regions = LL/RS
#define NTOPK 4
#define QKVC  768
#define HID   1024

// ---------------- scratch (device globals; no allocations allowed) ----------
__device__ float g_spk [NROWS*DIM];      // spikes s1 / s2 (reused)
__device__ float g_qkv [NROWS*QKVC];     // q|k|v
__device__ float g_qr  [LT*BB*RR*DIM];
__device__ float g_kr  [LT*BB*RR*DIM];
__device__ int   g_idx [LT*BB*RR*NTOPK];
__device__ float g_attn[NROWS*DIM];
__device__ float g_x1  [NROWS*DIM];
__device__ float g_h   [NROWS*HID];
__device__ float g_psum[128*DIM];
__device__ float g_psq [128*DIM];
__device__ float g_mean[DIM];
__device__ float g_var [DIM];

// ---------------- batchnorm stats (deterministic 2-stage) -------------------
__global__ void stats1(const float* __restrict__ in) {
    int blk = blockIdx.x, d = threadIdx.x;       // 128 blocks x 256 thr
    float s = 0.f, sq = 0.f;
    int r0 = blk * 256;
    for (int i = 0; i < 256; i++) {
        float v = in[(size_t)(r0 + i) * DIM + d];
        s += v; sq += v * v;
    }
    g_psum[blk*DIM + d] = s;
    g_psq [blk*DIM + d] = sq;
}

__global__ void stats2() {
    int d = threadIdx.x;
    float s = 0.f, sq = 0.f;
    for (int b = 0; b < 128; b++) { s += g_psum[b*DIM+d]; sq += g_psq[b*DIM+d]; }
    float mu = s / (float)NROWS;
    float var = sq / (float)NROWS - mu * mu;
    g_mean[d] = mu;
    g_var[d]  = var > 0.f ? var : 0.f;
}

// ---------------- batchnorm apply + LIF over time -> spikes -----------------
__global__ void bnlif(const float* __restrict__ in,
                      const float* __restrict__ gamma,
                      const float* __restrict__ beta) {
    int tid = blockIdx.x * 256 + threadIdx.x;    // over (b,l,d) = 2M
    int d = tid & 255;
    float mu = g_mean[d];
    float iv = 1.0f / sqrtf(g_var[d] + 1e-5f);
    float ga = gamma[d], be = beta[d];
    const size_t stride = (size_t)BB * LL * DIM;
    size_t base = (size_t)tid;
    float v = 0.f;
    #pragma unroll
    for (int t = 0; t < LT; t++) {
        float xt = (in[base + t*stride] - mu) * iv * ga + be;
        v += (xt - v) * 0.5f;                    // TAU = 2
        float sp;
        if (v >= 1.0f) { sp = 1.f; v = 0.f; } else sp = 0.f;
        g_spk[base + t*stride] = sp;
    }
}

// ---------------- sparse (binary-activation) GEMM: out = spk @ W + b --------
template <int C, bool GELU>
__global__ void spgemm(const float* __restrict__ W,
                       const float* __restrict__ bias,
                       float* __restrict__ out) {
    int n = blockIdx.x, tid = threadIdx.x;
    __shared__ int list[256];
    __shared__ unsigned masks[8];
    __shared__ int offs[9];
    float sv = g_spk[(size_t)n * DIM + tid];
    unsigned m = __ballot_sync(0xffffffffu, sv > 0.5f);
    int warp = tid >> 5, lane = tid & 31;
    if (lane == 0) masks[warp] = m;
    __syncthreads();
    if (tid == 0) {
        int o = 0;
        #pragma unroll
        for (int w = 0; w < 8; w++) { offs[w] = o; o += __popc(masks[w]); }
        offs[8] = o;
    }
    __syncthreads();
    if (sv > 0.5f)
        list[offs[warp] + __popc(m & ((1u << lane) - 1u))] = tid;
    int cnt = offs[8];
    __syncthreads();

    const int ncols = C * 256;
    float acc[C];
    #pragma unroll
    for (int c = 0; c < C; c++) acc[c] = bias[c*256 + tid];
    for (int i = 0; i < cnt; i++) {
        const float* wr = W + (size_t)list[i] * ncols;
        #pragma unroll
        for (int c = 0; c < C; c++) acc[c] += wr[c*256 + tid];
    }
    if (GELU) {
        #pragma unroll
        for (int c = 0; c < C; c++) {
            float x = acc[c];
            acc[c] = 0.5f * x * (1.f + erff(x * 0.70710678118654752f));
        }
    }
    float* op = out + (size_t)n * ncols;
    #pragma unroll
    for (int c = 0; c < C; c++) op[c*256 + tid] = acc[c];
}

// ---------------- region means of q,k ---------------------------------------
__global__ void regmean() {                      // 512 blocks x 256 thr
    int blk = blockIdx.x, d = threadIdx.x;
    int n0 = (blk >> 4) * LL + (blk & 15) * RS;
    float sq = 0.f, sk = 0.f;
    for (int i = 0; i < RS; i++) {
        const float* p = g_qkv + (size_t)(n0 + i) * QKVC + d;
        sq += p[0];
        sk += p[DIM];
    }
    g_qr[blk*DIM + d] = sq * (1.f/RS);
    g_kr[blk*DIM + d] = sk * (1.f/RS);
}

// ---------------- region affinity + top-k -----------------------------------
__global__ void afftopk() {                      // 32 blocks x 256 thr
    __shared__ float qs[16][257];
    __shared__ float ks[16][257];
    __shared__ float aff[16][17];
    int tb = blockIdx.x, tid = threadIdx.x;
    for (int idx = tid; idx < 16*256; idx += 256) {
        int rr = idx >> 8, d = idx & 255;
        qs[rr][d] = g_qr[(tb*16 + rr)*DIM + d];
        ks[rr][d] = g_kr[(tb*16 + rr)*DIM + d];
    }
    __syncthreads();
    int r = tid >> 4, s = tid & 15;
    float a = 0.f;
    #pragma unroll 8
    for (int d = 0; d < 256; d++) a += qs[r][d] * ks[s][d];
    aff[r][s] = a;
    __syncthreads();
    if (tid < 16) {
        float vals[16];
        #pragma unroll
        for (int s2 = 0; s2 < 16; s2++) vals[s2] = aff[tid][s2];
        #pragma unroll
        for (int m = 0; m < NTOPK; m++) {
            int best = 0; float bv = vals[0];
            #pragma unroll
            for (int s2 = 1; s2 < 16; s2++)
                if (vals[s2] > bv) { bv = vals[s2]; best = s2; }
            g_idx[(tb*16 + tid)*NTOPK + m] = best;
            vals[best] = -1e30f;
        }
    }
}

// ---------------- bi-level attention (per t,b,region,head) ------------------
__global__ void attn_kernel() {                  // 4096 blocks x 64 thr
    int bid = blockIdx.x;
    int h  = bid & 7;
    int r  = (bid >> 3) & 15;
    int tb = bid >> 7;
    int i  = threadIdx.x;
    int nq = tb * LL + r * RS + i;
    const float* qp = g_qkv + (size_t)nq * QKVC + h * HD;
    float4 q4[8];
    #pragma unroll
    for (int d = 0; d < 8; d++) q4[d] = *(const float4*)(qp + d*4);
    float4 o4[8];
    #pragma unroll
    for (int d = 0; d < 8; d++) o4[d] = make_float4(0.f,0.f,0.f,0.f);
    float lsum = 0.f;
    __shared__ float4 Ks[64*8];
    __shared__ float4 Vs[64*8];
    const float sc_hd = 0.17677669529663687f;    // 1/sqrt(32)
    for (int reg = 0; reg < NTOPK; reg++) {
        int s = g_idx[(tb*RR + r)*NTOPK + reg];
        int nk = tb * LL + s * RS + i;
        const float* kp = g_qkv + (size_t)nk * QKVC + DIM + h * HD;
        const float* vp = kp + DIM;
        #pragma unroll
        for (int d = 0; d < 8; d++) {
            Ks[i*8 + d] = *(const float4*)(kp + d*4);
            Vs[i*8 + d] = *(const float4*)(vp + d*4);
        }
        __syncthreads();
        for (int j = 0; j < 64; j++) {
            float sc = 0.f;
            #pragma unroll
            for (int d = 0; d < 8; d++) {
                float4 kk = Ks[j*8 + d];
                sc += q4[d].x*kk.x + q4[d].y*kk.y + q4[d].z*kk.z + q4[d].w*kk.w;
            }
            float e = __expf(sc * sc_hd);
            lsum += e;
            #pragma unroll
            for (int d = 0; d < 8; d++) {
                float4 vv = Vs[j*8 + d];
                o4[d].x += e*vv.x; o4[d].y += e*vv.y;
                o4[d].z += e*vv.z; o4[d].w += e*vv.w;
            }
        }
        __syncthreads();
    }
    float inv = 1.f / lsum;
    float* op = g_attn + (size_t)nq * DIM + h * HD;
    #pragma unroll
    for (int d = 0; d < 8; d++) {
        float4 o = o4[d];
        o.x *= inv; o.y *= inv; o.z *= inv; o.w *= inv;
        *(float4*)(op + d*4) = o;
    }
}

// ---------------- tf32 tensor-core GEMM with residual epilogue --------------
// out[M,256] = res + scale * (A[M,K] @ B[K,256] + bias)
// block tile 128x128, k-tile 32; 8 warps (4 over M, 2 over N)
__device__ __forceinline__ float tf32r(float x) {
    uint32_t u;
    asm("cvt.rna.tf32.f32 %0, %1;" : "=r"(u) : "f"(x));
    return __uint_as_float(u);
}

__device__ __forceinline__ void mma_tf32(float* d, const uint32_t* a, const uint32_t* b) {
    asm volatile(
        "mma.sync.aligned.m16n8k8.row.col.f32.tf32.tf32.f32 "
        "{%0,%1,%2,%3}, {%4,%5,%6,%7}, {%8,%9}, {%0,%1,%2,%3};\n"
        : "+f"(d[0]), "+f"(d[1]), "+f"(d[2]), "+f"(d[3])
        : "r"(a[0]), "r"(a[1]), "r"(a[2]), "r"(a[3]), "r"(b[0]), "r"(b[1]));
}

__global__ void gemm_tf32_res(const float* __restrict__ A,
                              const float* __restrict__ B,
                              const float* __restrict__ bias,
                              const float* __restrict__ res,
                              const float* __restrict__ scale_p,
                              float* __restrict__ out,
                              int K) {
    __shared__ float As[128*32];   // phys: row*32 + 4*(k4 ^ (row&7)) + (k&3)
    __shared__ float Bs[32*128];   // phys: k*128 + 4*(n4 ^ (2*(k&3))) + (n&3)
    int t = threadIdx.x;
    int lane = t & 31, warp = t >> 5;
    int warp_m = warp & 3;         // 4 warps x 32 rows
    int warp_n = warp >> 2;        // 2 warps x 64 cols
    int row0 = blockIdx.y * 128, col0 = blockIdx.x * 128;

    float acc[2][8][4];
    #pragma unroll
    for (int mt = 0; mt < 2; mt++)
        #pragma unroll
        for (int nt = 0; nt < 8; nt++)
            #pragma unroll
            for (int q = 0; q < 4; q++) acc[mt][nt][q] = 0.f;

    const float* Ag = A + (size_t)row0 * K;
    const float* Bg = B + col0;

    float4 pa[4], pb[4];
    // preload k-tile 0
    #pragma unroll
    for (int i = 0; i < 4; i++) {
        int flat = i*256 + t;
        pa[i] = *(const float4*)(Ag + (size_t)(flat >> 3)*K + (flat & 7)*4);
        pb[i] = *(const float4*)(Bg + (size_t)(flat >> 5)*256 + (flat & 31)*4);
    }
    #pragma unroll
    for (int i = 0; i < 4; i++) {
        int flat = i*256 + t;
        int ar = flat >> 3, ak4 = flat & 7;
        float4 w = make_float4(tf32r(pa[i].x), tf32r(pa[i].y), tf32r(pa[i].z), tf32r(pa[i].w));
        *(float4*)&As[ar*32 + 4*(ak4 ^ (ar & 7))] = w;
        int bk = flat >> 5, bc4 = flat & 31;
        float4 v = make_float4(tf32r(pb[i].x), tf32r(pb[i].y), tf32r(pb[i].z), tf32r(pb[i].w));
        *(float4*)&Bs[bk*128 + 4*(bc4 ^ (2*(bk & 3)))] = v;
    }
    __syncthreads();

    int nkt = K >> 5;
    for (int kt = 1; kt <= nkt; kt++) {
        if (kt < nkt) {
            int k0 = kt * 32;
            #pragma unroll
            for (int i = 0; i < 4; i++) {
                int flat = i*256 + t;
                pa[i] = *(const float4*)(Ag + (size_t)(flat >> 3)*K + k0 + (flat & 7)*4);
                pb[i] = *(const float4*)(Bg + (size_t)(k0 + (flat >> 5))*256 + (flat & 31)*4);
            }
        }
        // compute on current smem tile
        int c = lane & 3, p = lane >> 2;
        #pragma unroll
        for (int ks = 0; ks < 4; ks++) {
            int kb = ks * 8;
            uint32_t bf[8][2];
            int xb = 8 * c;
            #pragma unroll
            for (int nt = 0; nt < 8; nt++) {
                int wn = warp_n*64 + nt*8 + p;
                bf[nt][0] = __float_as_uint(Bs[(kb + c)*128 + (wn ^ xb)]);
                bf[nt][1] = __float_as_uint(Bs[(kb + 4 + c)*128 + (wn ^ xb)]);
            }
            #pragma unroll
            for (int mt = 0; mt < 2; mt++) {
                int rm = warp_m*32 + mt*16 + p;
                int xr = 4 * (rm & 7);
                uint32_t af[4];
                af[0] = __float_as_uint(As[rm*32 + ((kb + c) ^ xr)]);
                af[1] = __float_as_uint(As[(rm + 8)*32 + ((kb + c) ^ xr)]);
                af[2] = __float_as_uint(As[rm*32 + ((kb + 4 + c) ^ xr)]);
                af[3] = __float_as_uint(As[(rm + 8)*32 + ((kb + 4 + c) ^ xr)]);
                #pragma unroll
                for (int nt = 0; nt < 8; nt++)
                    mma_tf32(acc[mt][nt], af, bf[nt]);
            }
        }
        __syncthreads();
        if (kt < nkt) {
            #pragma unroll
            for (int i = 0; i < 4; i++) {
                int flat = i*256 + t;
                int ar = flat >> 3, ak4 = flat & 7;
                float4 w = make_float4(tf32r(pa[i].x), tf32r(pa[i].y), tf32r(pa[i].z), tf32r(pa[i].w));
                *(float4*)&As[ar*32 + 4*(ak4 ^ (ar & 7))] = w;
                int bk = flat >> 5, bc4 = flat & 31;
                float4 v = make_float4(tf32r(pb[i].x), tf32r(pb[i].y), tf32r(pb[i].z), tf32r(pb[i].w));
                *(float4*)&Bs[bk*128 + 4*(bc4 ^ (2*(bk & 3)))] = v;
            }
            __syncthreads();
        }
    }

    // epilogue: out = res + sc*(acc + bias)
    float sc = *scale_p;
    int c = lane & 3, p = lane >> 2;
    #pragma unroll
    for (int mt = 0; mt < 2; mt++) {
        int r = row0 + warp_m*32 + mt*16 + p;
        #pragma unroll
        for (int nt = 0; nt < 8; nt++) {
            int cc = col0 + warp_n*64 + nt*8 + 2*c;
            float b0v = bias[cc], b1v = bias[cc + 1];
            size_t o1 = (size_t)r*256 + cc;
            float2 r1 = *(const float2*)(res + o1);
            float2 w1;
            w1.x = r1.x + sc*(acc[mt][nt][0] + b0v);
            w1.y = r1.y + sc*(acc[mt][nt][1] + b1v);
            *(float2*)(out + o1) = w1;
            size_t o2 = o1 + 8*256;
            float2 r2 = *(const float2*)(res + o2);
            float2 w2;
            w2.x = r2.x + sc*(acc[mt][nt][2] + b0v);
            w2.y = r2.y + sc*(acc[mt][nt][3] + b1v);
            *(float2*)(out + o2) = w2;
        }
    }
}

// ---------------- launch -----------------------------------------------------
extern "C" void kernel_launch(void* const* d_in, const int* in_sizes, int n_in,
                              void* d_out, int out_size) {
    const float* x     = (const float*)d_in[0];
    const float* bn1_g = (const float*)d_in[1];
    const float* bn1_b = (const float*)d_in[2];
    const float* Wqkv  = (const float*)d_in[3];
    const float* bqkv  = (const float*)d_in[4];
    const float* Wo    = (const float*)d_in[5];
    const float* bo    = (const float*)d_in[6];
    const float* bn2_g = (const float*)d_in[7];
    const float* bn2_b = (const float*)d_in[8];
    const float* W1    = (const float*)d_in[9];
    const float* b1    = (const float*)d_in[10];
    const float* W2    = (const float*)d_in[11];
    const float* b2    = (const float*)d_in[12];
    const float* scale = (const float*)d_in[13];
    float* out = (float*)d_out;

    float *p_x1, *p_attn, *p_h, *p_qkv;
    cudaGetSymbolAddress((void**)&p_x1,   g_x1);
    cudaGetSymbolAddress((void**)&p_attn, g_attn);
    cudaGetSymbolAddress((void**)&p_h,    g_h);
    cudaGetSymbolAddress((void**)&p_qkv,  g_qkv);

    // stage 1: bn1 + LIF -> s1
    stats1<<<128, 256>>>(x);
    stats2<<<1, 256>>>();
    bnlif<<<(BB*LL*DIM)/256, 256>>>(x, bn1_g, bn1_b);

    // qkv = s1 @ Wqkv + bqkv (sparse binary gather)
    spgemm<3, false><<<NROWS, 256>>>(Wqkv, bqkv, p_qkv);

    // region means, affinity, top-k, attention
    regmean<<<512, 256>>>();
    afftopk<<<32, 256>>>();
    attn_kernel<<<LT*BB*RR*HEADS, 64>>>();

    // x1 = x + scale * (attn @ Wo + bo)   [tf32 tensor core]
    dim3 gg(2, NROWS/128);
    gemm_tf32_res<<<gg, 256>>>(p_attn, Wo, bo, x, scale, p_x1, DIM);

    // stage 2: bn2 + LIF -> s2
    stats1<<<128, 256>>>(p_x1);
    stats2<<<1, 256>>>();
    bnlif<<<(BB*LL*DIM)/256, 256>>>(p_x1, bn2_g, bn2_b);

    // h = gelu(s2 @ W1 + b1) (sparse binary gather)
    spgemm<4, true><<<NROWS, 256>>>(W1, b1, p_h);

    // out = x1 + scale * (h @ W2 + b2)   [tf32 tensor core]
    gemm_tf32_res<<<gg, 256>>>(p_h, W2, b2, p_x1, scale, out, HID);
}

// round 3
// speedup vs baseline: 2.4416x; 1.6592x over previous
#include <cuda_runtime.h>
#include <cuda_bf16.h>
#include <math.h>
#include <stdint.h>

#define LT   4
#define BB   8
#define LL   1024
#define DIM  256
#define NROWS (LT*BB*LL)     // 32768
#define HEADS 8
#define HD    32
#define RS    64
#define RR    16              // regions = LL/RS
#define NTOPK 4
#define QKVC  768
#define HID   1024

// ---------------- scratch (device globals; no allocations allowed) ----------
__device__ float g_spk [NROWS*DIM];
__device__ float g_qkv [NROWS*QKVC];
__device__ float g_qr  [LT*BB*RR*DIM];
__device__ float g_kr  [LT*BB*RR*DIM];
__device__ int   g_idx [LT*BB*RR*NTOPK];
__device__ float g_attn[NROWS*DIM];
__device__ float g_x1  [NROWS*DIM];
__device__ float g_h   [NROWS*HID];
__device__ float g_psum[128*DIM];
__device__ float g_psq [128*DIM];
__device__ float g_mean[DIM];
__device__ float g_var [DIM];

// ---------------- batchnorm stats -------------------------------------------
__global__ void stats1(const float* __restrict__ in) {
    int blk = blockIdx.x, d = threadIdx.x;
    float s = 0.f, sq = 0.f;
    int r0 = blk * 256;
    for (int i = 0; i < 256; i++) {
        float v = in[(size_t)(r0 + i) * DIM + d];
        s += v; sq += v * v;
    }
    g_psum[blk*DIM + d] = s;
    g_psq [blk*DIM + d] = sq;
}

__global__ void stats2() {
    int d = threadIdx.x;
    float s = 0.f, sq = 0.f;
    for (int b = 0; b < 128; b++) { s += g_psum[b*DIM+d]; sq += g_psq[b*DIM+d]; }
    float mu = s / (float)NROWS;
    float var = sq / (float)NROWS - mu * mu;
    g_mean[d] = mu;
    g_var[d]  = var > 0.f ? var : 0.f;
}

// ---------------- batchnorm + LIF -------------------------------------------
__global__ void bnlif(const float* __restrict__ in,
                      const float* __restrict__ gamma,
                      const float* __restrict__ beta) {
    int tid = blockIdx.x * 256 + threadIdx.x;
    int d = tid & 255;
    float mu = g_mean[d];
    float iv = 1.0f / sqrtf(g_var[d] + 1e-5f);
    float ga = gamma[d], be = beta[d];
    const size_t stride = (size_t)BB * LL * DIM;
    size_t base = (size_t)tid;
    float v = 0.f;
    #pragma unroll
    for (int t = 0; t < LT; t++) {
        float xt = (in[base + t*stride] - mu) * iv * ga + be;
        v += (xt - v) * 0.5f;
        float sp;
        if (v >= 1.0f) { sp = 1.f; v = 0.f; } else sp = 0.f;
        g_spk[base + t*stride] = sp;
    }
}

// ---------------- sparse binary GEMM (float4) -------------------------------
template <int C, bool GELU>
__global__ void spgemm(const float* __restrict__ W,
                       const float* __restrict__ bias,
                       float* __restrict__ out) {
    int n = blockIdx.x, tid = threadIdx.x;
    __shared__ int list[256];
    __shared__ unsigned masks[8];
    __shared__ int offs[9];
    float sv = g_spk[(size_t)n * DIM + tid];
    unsigned m = __ballot_sync(0xffffffffu, sv > 0.5f);
    int warp = tid >> 5, lane = tid & 31;
    if (lane == 0) masks[warp] = m;
    __syncthreads();
    if (tid == 0) {
        int o = 0;
        #pragma unroll
        for (int w = 0; w < 8; w++) { offs[w] = o; o += __popc(masks[w]); }
        offs[8] = o;
    }
    __syncthreads();
    if (sv > 0.5f)
        list[offs[warp] + __popc(m & ((1u << lane) - 1u))] = tid;
    int cnt = offs[8];
    __syncthreads();

    const int NC4 = C * 64;                  // float4 columns
    if (tid < NC4) {
        const float4* W4 = (const float4*)W;
        float4 acc = ((const float4*)bias)[tid];
        for (int i = 0; i < cnt; i++) {
            float4 w = W4[(size_t)list[i] * NC4 + tid];
            acc.x += w.x; acc.y += w.y; acc.z += w.z; acc.w += w.w;
        }
        if (GELU) {
            acc.x = 0.5f*acc.x*(1.f + erff(acc.x*0.70710678118654752f));
            acc.y = 0.5f*acc.y*(1.f + erff(acc.y*0.70710678118654752f));
            acc.z = 0.5f*acc.z*(1.f + erff(acc.z*0.70710678118654752f));
            acc.w = 0.5f*acc.w*(1.f + erff(acc.w*0.70710678118654752f));
        }
        ((float4*)(out + (size_t)n * C * 256))[tid] = acc;
    }
}

// ---------------- region means ----------------------------------------------
__global__ void regmean() {
    int blk = blockIdx.x, d = threadIdx.x;
    int n0 = (blk >> 4) * LL + (blk & 15) * RS;
    float sq = 0.f, sk = 0.f;
    for (int i = 0; i < RS; i++) {
        const float* p = g_qkv + (size_t)(n0 + i) * QKVC + d;
        sq += p[0];
        sk += p[DIM];
    }
    g_qr[blk*DIM + d] = sq * (1.f/RS);
    g_kr[blk*DIM + d] = sk * (1.f/RS);
}

// ---------------- region affinity + top-k -----------------------------------
__global__ void afftopk() {
    __shared__ float qs[16][257];
    __shared__ float ks[16][257];
    __shared__ float aff[16][17];
    int tb = blockIdx.x, tid = threadIdx.x;
    for (int idx = tid; idx < 16*256; idx += 256) {
        int rr = idx >> 8, d = idx & 255;
        qs[rr][d] = g_qr[(tb*16 + rr)*DIM + d];
        ks[rr][d] = g_kr[(tb*16 + rr)*DIM + d];
    }
    __syncthreads();
    int r = tid >> 4, s = tid & 15;
    float a = 0.f;
    #pragma unroll 8
    for (int d = 0; d < 256; d++) a += qs[r][d] * ks[s][d];
    aff[r][s] = a;
    __syncthreads();
    if (tid < 16) {
        float vals[16];
        #pragma unroll
        for (int s2 = 0; s2 < 16; s2++) vals[s2] = aff[tid][s2];
        #pragma unroll
        for (int m = 0; m < NTOPK; m++) {
            int best = 0; float bv = vals[0];
            #pragma unroll
            for (int s2 = 1; s2 < 16; s2++)
                if (vals[s2] > bv) { bv = vals[s2]; best = s2; }
            g_idx[(tb*16 + tid)*NTOPK + m] = best;
            vals[best] = -1e30f;
        }
    }
}

// ---------------- bf16 mma helpers ------------------------------------------
__device__ __forceinline__ uint32_t pk2(float a, float b) {
    __nv_bfloat162 h = __floats2bfloat162_rn(a, b);   // x=a (low), y=b (high)
    return *(uint32_t*)&h;
}

__device__ __forceinline__ void mma_bf16(float* d, const uint32_t* a, const uint32_t* b) {
    asm volatile(
        "mma.sync.aligned.m16n8k16.row.col.f32.bf16.bf16.f32 "
        "{%0,%1,%2,%3}, {%4,%5,%6,%7}, {%8,%9}, {%0,%1,%2,%3};\n"
        : "+f"(d[0]), "+f"(d[1]), "+f"(d[2]), "+f"(d[3])
        : "r"(a[0]), "r"(a[1]), "r"(a[2]), "r"(a[3]), "r"(b[0]), "r"(b[1]));
}

// exp(s * 1/sqrt(32)) via exp2 poly on FMA pipe (no MUFU)
__device__ __forceinline__ float fexp_sc(float s) {
    const float C = 0.17677669529663687f * 1.4426950408889634f;
    float y = s * C;
    float z = y + 12582912.f;              // round-to-int magic
    float n = z - 12582912.f;
    float f = y - n;                       // f in [-0.5, 0.5]
    float p = 0.0013333558f;
    p = fmaf(p, f, 0.0096181291f);
    p = fmaf(p, f, 0.0555041087f);
    p = fmaf(p, f, 0.2402265069f);
    p = fmaf(p, f, 0.6931471806f);
    p = fmaf(p, f, 1.0f);
    return __int_as_float(__float_as_int(p) + (__float_as_int(z) << 23));
}

// ---------------- bi-level attention (tensor cores) -------------------------
// grid 4096 = (tb*128 + r*8 + h), 64 threads (2 warps x 32 q-rows)
__global__ void attn_mma() {
    int bid = blockIdx.x;
    int h  = bid & 7;
    int r  = (bid >> 3) & 15;
    int tb = bid >> 7;
    int t = threadIdx.x, lane = t & 31, w = t >> 5;

    __shared__ __nv_bfloat16 Ks[64*40];     // [j][d] rows padded to 40 halves
    __shared__ __nv_bfloat16 Vt[32*72];     // [d][j] rows padded to 72 halves

    int rlo  = lane >> 2;          // 0..7
    int qcol = (lane & 3) * 2;     // 0,2,4,6

    // Q fragments: A m16k16, 2 m-tiles x 2 k-tiles
    uint32_t qf[2][2][4];
    int qr_base = tb * LL + r * RS + w * 32;
    #pragma unroll
    for (int mt = 0; mt < 2; mt++) {
        #pragma unroll
        for (int kt = 0; kt < 2; kt++) {
            const float* qp = g_qkv + (size_t)(qr_base + mt*16 + rlo) * QKVC + h*HD + kt*16 + qcol;
            float2 v0 = *(const float2*)(qp);
            float2 v1 = *(const float2*)(qp + 8*QKVC);
            float2 v2 = *(const float2*)(qp + 8);
            float2 v3 = *(const float2*)(qp + 8*QKVC + 8);
            qf[mt][kt][0] = pk2(v0.x, v0.y);
            qf[mt][kt][1] = pk2(v1.x, v1.y);
            qf[mt][kt][2] = pk2(v2.x, v2.y);
            qf[mt][kt][3] = pk2(v3.x, v3.y);
        }
    }

    float oacc[2][4][4];
    #pragma unroll
    for (int mt = 0; mt < 2; mt++)
        #pragma unroll
        for (int nt = 0; nt < 4; nt++)
            #pragma unroll
            for (int q = 0; q < 4; q++) oacc[mt][nt][q] = 0.f;
    float rs[2][2] = {{0.f,0.f},{0.f,0.f}};

    for (int reg = 0; reg < NTOPK; reg++) {
        int s = g_idx[(tb*RR + r)*NTOPK + reg];
        int kvbase = tb * LL + s * RS;
        // load K region tile [64 x 32] and V transposed [32 x 64]
        #pragma unroll
        for (int i = 0; i < 16; i++) {
            int flat = i*64 + t;            // 0..1023
            int j  = flat >> 4;             // 0..63
            int d2 = (flat & 15) * 2;       // 0..30
            const float* kp = g_qkv + (size_t)(kvbase + j)*QKVC + DIM + h*HD + d2;
            float2 kv = *(const float2*)kp;
            float2 vv = *(const float2*)(kp + DIM);
            *(uint32_t*)&Ks[j*40 + d2] = pk2(kv.x, kv.y);
            Vt[d2*72 + j]     = __float2bfloat16(vv.x);
            Vt[(d2+1)*72 + j] = __float2bfloat16(vv.y);
        }
        __syncthreads();

        // scores S[32x64] = Q @ K^T
        float sacc[2][8][4];
        #pragma unroll
        for (int mt = 0; mt < 2; mt++)
            #pragma unroll
            for (int nt = 0; nt < 8; nt++)
                #pragma unroll
                for (int q = 0; q < 4; q++) sacc[mt][nt][q] = 0.f;

        #pragma unroll
        for (int kt = 0; kt < 2; kt++) {
            #pragma unroll
            for (int nt = 0; nt < 8; nt++) {
                int j = nt*8 + rlo;
                int a0 = j*40 + kt*16 + qcol;
                uint32_t b0 = *(uint32_t*)&Ks[a0];
                uint32_t b1 = *(uint32_t*)&Ks[a0 + 8];
                uint32_t bfr[2] = {b0, b1};
                mma_bf16(sacc[0][nt], qf[0][kt], bfr);
                mma_bf16(sacc[1][nt], qf[1][kt], bfr);
            }
        }

        // exp + row sums + pack P as A-fragments
        uint32_t pf[2][4][4];
        #pragma unroll
        for (int mt = 0; mt < 2; mt++) {
            #pragma unroll
            for (int nt = 0; nt < 8; nt++) {
                float e0 = fexp_sc(sacc[mt][nt][0]);
                float e1 = fexp_sc(sacc[mt][nt][1]);
                float e2 = fexp_sc(sacc[mt][nt][2]);
                float e3 = fexp_sc(sacc[mt][nt][3]);
                rs[mt][0] += e0 + e1;
                rs[mt][1] += e2 + e3;
                int kt2 = nt >> 1;
                if ((nt & 1) == 0) {
                    pf[mt][kt2][0] = pk2(e0, e1);
                    pf[mt][kt2][1] = pk2(e2, e3);
                } else {
                    pf[mt][kt2][2] = pk2(e0, e1);
                    pf[mt][kt2][3] = pk2(e2, e3);
                }
            }
        }

        // O += P @ V
        #pragma unroll
        for (int kt2 = 0; kt2 < 4; kt2++) {
            #pragma unroll
            for (int nv = 0; nv < 4; nv++) {
                int d = nv*8 + rlo;
                int j0 = kt2*16 + qcol;
                uint32_t b0 = *(uint32_t*)&Vt[d*72 + j0];
                uint32_t b1 = *(uint32_t*)&Vt[d*72 + j0 + 8];
                uint32_t bfr[2] = {b0, b1};
                mma_bf16(oacc[0][nv], pf[0][kt2], bfr);
                mma_bf16(oacc[1][nv], pf[1][kt2], bfr);
            }
        }
        __syncthreads();
    }

    // rowsum reduce across the 4 lanes sharing a row
    #pragma unroll
    for (int mt = 0; mt < 2; mt++)
        #pragma unroll
        for (int i = 0; i < 2; i++) {
            float v = rs[mt][i];
            v += __shfl_xor_sync(0xffffffffu, v, 1);
            v += __shfl_xor_sync(0xffffffffu, v, 2);
            rs[mt][i] = 1.f / v;
        }

    // write O
    #pragma unroll
    for (int mt = 0; mt < 2; mt++) {
        int row0 = qr_base + mt*16 + rlo;
        #pragma unroll
        for (int nv = 0; nv < 4; nv++) {
            int d = h*HD + nv*8 + qcol;
            float2 w0, w1;
            w0.x = oacc[mt][nv][0] * rs[mt][0];
            w0.y = oacc[mt][nv][1] * rs[mt][0];
            w1.x = oacc[mt][nv][2] * rs[mt][1];
            w1.y = oacc[mt][nv][3] * rs[mt][1];
            *(float2*)(g_attn + (size_t)row0*DIM + d)     = w0;
            *(float2*)(g_attn + (size_t)(row0+8)*DIM + d) = w1;
        }
    }
}

// ---------------- tf32 tensor-core GEMM with residual epilogue --------------
__device__ __forceinline__ float tf32r(float x) {
    uint32_t u;
    asm("cvt.rna.tf32.f32 %0, %1;" : "=r"(u) : "f"(x));
    return __uint_as_float(u);
}

__device__ __forceinline__ void mma_tf32(float* d, const uint32_t* a, const uint32_t* b) {
    asm volatile(
        "mma.sync.aligned.m16n8k8.row.col.f32.tf32.tf32.f32 "
        "{%0,%1,%2,%3}, {%4,%5,%6,%7}, {%8,%9}, {%0,%1,%2,%3};\n"
        : "+f"(d[0]), "+f"(d[1]), "+f"(d[2]), "+f"(d[3])
        : "r"(a[0]), "r"(a[1]), "r"(a[2]), "r"(a[3]), "r"(b[0]), "r"(b[1]));
}

__global__ void gemm_tf32_res(const float* __restrict__ A,
                              const float* __restrict__ B,
                              const float* __restrict__ bias,
                              const float* __restrict__ res,
                              const float* __restrict__ scale_p,
                              float* __restrict__ out,
                              int K) {
    __shared__ float As[128*32];
    __shared__ float Bs[32*128];
    int t = threadIdx.x;
    int lane = t & 31, warp = t >> 5;
    int warp_m = warp & 3;
    int warp_n = warp >> 2;
    int row0 = blockIdx.y * 128, col0 = blockIdx.x * 128;

    float acc[2][8][4];
    #pragma unroll
    for (int mt = 0; mt < 2; mt++)
        #pragma unroll
        for (int nt = 0; nt < 8; nt++)
            #pragma unroll
            for (int q = 0; q < 4; q++) acc[mt][nt][q] = 0.f;

    const float* Ag = A + (size_t)row0 * K;
    const float* Bg = B + col0;

    float4 pa[4], pb[4];
    #pragma unroll
    for (int i = 0; i < 4; i++) {
        int flat = i*256 + t;
        pa[i] = *(const float4*)(Ag + (size_t)(flat >> 3)*K + (flat & 7)*4);
        pb[i] = *(const float4*)(Bg + (size_t)(flat >> 5)*256 + (flat & 31)*4);
    }
    #pragma unroll
    for (int i = 0; i < 4; i++) {
        int flat = i*256 + t;
        int ar = flat >> 3, ak4 = flat & 7;
        float4 wv = make_float4(tf32r(pa[i].x), tf32r(pa[i].y), tf32r(pa[i].z), tf32r(pa[i].w));
        *(float4*)&As[ar*32 + 4*(ak4 ^ (ar & 7))] = wv;
        int bk = flat >> 5, bc4 = flat & 31;
        float4 v = make_float4(tf32r(pb[i].x), tf32r(pb[i].y), tf32r(pb[i].z), tf32r(pb[i].w));
        *(float4*)&Bs[bk*128 + 4*(bc4 ^ (2*(bk & 3)))] = v;
    }
    __syncthreads();

    int nkt = K >> 5;
    for (int kt = 1; kt <= nkt; kt++) {
        if (kt < nkt) {
            int k0 = kt * 32;
            #pragma unroll
            for (int i = 0; i < 4; i++) {
                int flat = i*256 + t;
                pa[i] = *(const float4*)(Ag + (size_t)(flat >> 3)*K + k0 + (flat & 7)*4);
                pb[i] = *(const float4*)(Bg + (size_t)(k0 + (flat >> 5))*256 + (flat & 31)*4);
            }
        }
        int c = lane & 3, p = lane >> 2;
        #pragma unroll
        for (int ks = 0; ks < 4; ks++) {
            int kb = ks * 8;
            uint32_t bf[8][2];
            int xb = 8 * c;
            #pragma unroll
            for (int nt = 0; nt < 8; nt++) {
                int wn = warp_n*64 + nt*8 + p;
                bf[nt][0] = __float_as_uint(Bs[(kb + c)*128 + (wn ^ xb)]);
                bf[nt][1] = __float_as_uint(Bs[(kb + 4 + c)*128 + (wn ^ xb)]);
            }
            #pragma unroll
            for (int mt = 0; mt < 2; mt++) {
                int rm = warp_m*32 + mt*16 + p;
                int xr = 4 * (rm & 7);
                uint32_t af[4];
                af[0] = __float_as_uint(As[rm*32 + ((kb + c) ^ xr)]);
                af[1] = __float_as_uint(As[(rm + 8)*32 + ((kb + c) ^ xr)]);
                af[2] = __float_as_uint(As[rm*32 + ((kb + 4 + c) ^ xr)]);
                af[3] = __float_as_uint(As[(rm + 8)*32 + ((kb + 4 + c) ^ xr)]);
                #pragma unroll
                for (int nt = 0; nt < 8; nt++)
                    mma_tf32(acc[mt][nt], af, bf[nt]);
            }
        }
        __syncthreads();
        if (kt < nkt) {
            #pragma unroll
            for (int i = 0; i < 4; i++) {
                int flat = i*256 + t;
                int ar = flat >> 3, ak4 = flat & 7;
                float4 wv = make_float4(tf32r(pa[i].x), tf32r(pa[i].y), tf32r(pa[i].z), tf32r(pa[i].w));
                *(float4*)&As[ar*32 + 4*(ak4 ^ (ar & 7))] = wv;
                int bk = flat >> 5, bc4 = flat & 31;
                float4 v = make_float4(tf32r(pb[i].x), tf32r(pb[i].y), tf32r(pb[i].z), tf32r(pb[i].w));
                *(float4*)&Bs[bk*128 + 4*(bc4 ^ (2*(bk & 3)))] = v;
            }
            __syncthreads();
        }
    }

    float sc = *scale_p;
    int c = lane & 3, p = lane >> 2;
    #pragma unroll
    for (int mt = 0; mt < 2; mt++) {
        int r = row0 + warp_m*32 + mt*16 + p;
        #pragma unroll
        for (int nt = 0; nt < 8; nt++) {
            int cc = col0 + warp_n*64 + nt*8 + 2*c;
            float b0v = bias[cc], b1v = bias[cc + 1];
            size_t o1 = (size_t)r*256 + cc;
            float2 r1 = *(const float2*)(res + o1);
            float2 w1;
            w1.x = r1.x + sc*(acc[mt][nt][0] + b0v);
            w1.y = r1.y + sc*(acc[mt][nt][1] + b1v);
            *(float2*)(out + o1) = w1;
            size_t o2 = o1 + 8*256;
            float2 r2 = *(const float2*)(res + o2);
            float2 w2;
            w2.x = r2.x + sc*(acc[mt][nt][2] + b0v);
            w2.y = r2.y + sc*(acc[mt][nt][3] + b1v);
            *(float2*)(out + o2) = w2;
        }
    }
}

// ---------------- launch -----------------------------------------------------
extern "C" void kernel_launch(void* const* d_in, const int* in_sizes, int n_in,
                              void* d_out, int out_size) {
    const float* x     = (const float*)d_in[0];
    const float* bn1_g = (const float*)d_in[1];
    const float* bn1_b = (const float*)d_in[2];
    const float* Wqkv  = (const float*)d_in[3];
    const float* bqkv  = (const float*)d_in[4];
    const float* Wo    = (const float*)d_in[5];
    const float* bo    = (const float*)d_in[6];
    const float* bn2_g = (const float*)d_in[7];
    const float* bn2_b = (const float*)d_in[8];
    const float* W1    = (const float*)d_in[9];
    const float* b1    = (const float*)d_in[10];
    const float* W2    = (const float*)d_in[11];
    const float* b2    = (const float*)d_in[12];
    const float* scale = (const float*)d_in[13];
    float* out = (float*)d_out;

    float *p_x1, *p_attn, *p_h, *p_qkv;
    cudaGetSymbolAddress((void**)&p_x1,   g_x1);
    cudaGetSymbolAddress((void**)&p_attn, g_attn);
    cudaGetSymbolAddress((void**)&p_h,    g_h);
    cudaGetSymbolAddress((void**)&p_qkv,  g_qkv);

    // stage 1: bn1 + LIF -> s1
    stats1<<<128, 256>>>(x);
    stats2<<<1, 256>>>();
    bnlif<<<(BB*LL*DIM)/256, 256>>>(x, bn1_g, bn1_b);

    // qkv = s1 @ Wqkv + bqkv
    spgemm<3, false><<<NROWS, 256>>>(Wqkv, bqkv, p_qkv);

    // region means, affinity, top-k, attention
    regmean<<<512, 256>>>();
    afftopk<<<32, 256>>>();
    attn_mma<<<LT*BB*RR*HEADS, 64>>>();

    // x1 = x + scale * (attn @ Wo + bo)
    dim3 gg(2, NROWS/128);
    gemm_tf32_res<<<gg, 256>>>(p_attn, Wo, bo, x, scale, p_x1, DIM);

    // stage 2: bn2 + LIF -> s2
    stats1<<<128, 256>>>(p_x1);
    stats2<<<1, 256>>>();
    bnlif<<<(BB*LL*DIM)/256, 256>>>(p_x1, bn2_g, bn2_b);

    // h = gelu(s2 @ W1 + b1)
    spgemm<4, true><<<NROWS, 256>>>(W1, b1, p_h);

    // out = x1 + scale * (h @ W2 + b2)
    gemm_tf32_res<<<gg, 256>>>(p_h, W2, b2, p_x1, scale, out, HID);
}

// round 5
// speedup vs baseline: 3.1514x; 1.2907x over previous
#include <cuda_runtime.h>
#include <cuda_bf16.h>
#include <math.h>
#include <stdint.h>

#define LT   4
#define BB   8
#define LL   1024
#define DIM  256
#define NROWS (LT*BB*LL)     // 32768
#define HEADS 8
#define HD    32
#define RS    64
#define RR    16
#define NTOPK 4
#define QKVC  768
#define HID   1024

// ---------------- scratch ----------------------------------------------------
__device__ float g_spk [NROWS*DIM];
__device__ float g_qkv [NROWS*QKVC];
__device__ float g_qr  [LT*BB*RR*DIM];
__device__ float g_kr  [LT*BB*RR*DIM];
__device__ int   g_idx [LT*BB*RR*NTOPK];
__device__ __nv_bfloat16 g_attn[NROWS*DIM];
__device__ float g_x1  [NROWS*DIM];
__device__ __nv_bfloat16 g_h   [NROWS*HID];
__device__ __nv_bfloat16 g_w1bf[DIM*HID];
__device__ float g_psum[128*DIM];
__device__ float g_psq [128*DIM];
__device__ float g_mean[DIM];
__device__ float g_var [DIM];

__device__ __forceinline__ uint32_t pk2(float a, float b) {
    __nv_bfloat162 h = __floats2bfloat162_rn(a, b);
    return *(uint32_t*)&h;
}
__device__ __forceinline__ uint32_t smem_u32(const void* p) {
    return (uint32_t)__cvta_generic_to_shared(p);
}

// ---------------- batchnorm stats -------------------------------------------
__global__ void stats1(const float* __restrict__ in) {
    int blk = blockIdx.x, d = threadIdx.x;
    float s = 0.f, sq = 0.f;
    int r0 = blk * 256;
    for (int i = 0; i < 256; i++) {
        float v = in[(size_t)(r0 + i) * DIM + d];
        s += v; sq += v * v;
    }
    g_psum[blk*DIM + d] = s;
    g_psq [blk*DIM + d] = sq;
}

__global__ void stats2() {
    int d = threadIdx.x;
    float s = 0.f, sq = 0.f;
    for (int b = 0; b < 128; b++) { s += g_psum[b*DIM+d]; sq += g_psq[b*DIM+d]; }
    float mu = s / (float)NROWS;
    float var = sq / (float)NROWS - mu * mu;
    g_mean[d] = mu;
    g_var[d]  = var > 0.f ? var : 0.f;
}

// ---------------- batchnorm + LIF -------------------------------------------
__global__ void bnlif(const float* __restrict__ in,
                      const float* __restrict__ gamma,
                      const float* __restrict__ beta) {
    int tid = blockIdx.x * 256 + threadIdx.x;
    int d = tid & 255;
    float mu = g_mean[d];
    float iv = 1.0f / sqrtf(g_var[d] + 1e-5f);
    float ga = gamma[d], be = beta[d];
    const size_t stride = (size_t)BB * LL * DIM;
    size_t base = (size_t)tid;
    float v = 0.f;
    #pragma unroll
    for (int t = 0; t < LT; t++) {
        float xt = (in[base + t*stride] - mu) * iv * ga + be;
        v += (xt - v) * 0.5f;
        float sp;
        if (v >= 1.0f) { sp = 1.f; v = 0.f; } else sp = 0.f;
        g_spk[base + t*stride] = sp;
    }
}

// ---------------- fp32 -> bf16 weight conversion ----------------------------
__global__ void cvtW(const float* __restrict__ src, __nv_bfloat16* __restrict__ dst) {
    int i = blockIdx.x * 256 + threadIdx.x;
    float4 v = ((const float4*)src)[i];
    uint2 o;
    o.x = pk2(v.x, v.y);
    o.y = pk2(v.z, v.w);
    ((uint2*)dst)[i] = o;
}

// ---------------- sparse binary GEMM: qkv (fp32, exact for top-k path) ------
__global__ void spgemm_qkv(const float* __restrict__ W,
                           const float* __restrict__ bias,
                           float* __restrict__ out) {
    int n = blockIdx.x, tid = threadIdx.x;
    __shared__ int list[256];
    __shared__ unsigned masks[8];
    __shared__ int offs[9];
    float sv = g_spk[(size_t)n * DIM + tid];
    unsigned m = __ballot_sync(0xffffffffu, sv > 0.5f);
    int warp = tid >> 5, lane = tid & 31;
    if (lane == 0) masks[warp] = m;
    __syncthreads();
    if (tid == 0) {
        int o = 0;
        #pragma unroll
        for (int w = 0; w < 8; w++) { offs[w] = o; o += __popc(masks[w]); }
        offs[8] = o;
    }
    __syncthreads();
    if (sv > 0.5f)
        list[offs[warp] + __popc(m & ((1u << lane) - 1u))] = tid;
    int cnt = offs[8];
    __syncthreads();

    if (tid < 192) {
        const float4* W4 = (const float4*)W;
        float4 acc = ((const float4*)bias)[tid];
        for (int i = 0; i < cnt; i++) {
            float4 w = W4[(size_t)list[i] * 192 + tid];
            acc.x += w.x; acc.y += w.y; acc.z += w.z; acc.w += w.w;
        }
        ((float4*)(out + (size_t)n * QKVC))[tid] = acc;
    }
}

// ---------------- sparse binary GEMM: MLP (bf16 W, bf16 out, gelu) ----------
__global__ void spgemm_mlp(const float* __restrict__ bias,
                           __nv_bfloat16* __restrict__ out) {
    int n = blockIdx.x, tid = threadIdx.x;
    __shared__ int list[256];
    __shared__ unsigned masks[8];
    __shared__ int offs[9];
    float sv = g_spk[(size_t)n * DIM + tid];
    unsigned m = __ballot_sync(0xffffffffu, sv > 0.5f);
    int warp = tid >> 5, lane = tid & 31;
    if (lane == 0) masks[warp] = m;
    __syncthreads();
    if (tid == 0) {
        int o = 0;
        #pragma unroll
        for (int w = 0; w < 8; w++) { offs[w] = o; o += __popc(masks[w]); }
        offs[8] = o;
    }
    __syncthreads();
    if (sv > 0.5f)
        list[offs[warp] + __popc(m & ((1u << lane) - 1u))] = tid;
    int cnt = offs[8];
    __syncthreads();

    float4 bv = ((const float4*)bias)[tid];
    float a0 = bv.x, a1 = bv.y, a2 = bv.z, a3 = bv.w;
    for (int i = 0; i < cnt; i++) {
        uint2 w = *(const uint2*)(g_w1bf + (size_t)list[i] * HID + tid * 4);
        float2 f0 = __bfloat1622float2(*(__nv_bfloat162*)&w.x);
        float2 f1 = __bfloat1622float2(*(__nv_bfloat162*)&w.y);
        a0 += f0.x; a1 += f0.y; a2 += f1.x; a3 += f1.y;
    }
    a0 = 0.5f*a0*(1.f + erff(a0*0.70710678118654752f));
    a1 = 0.5f*a1*(1.f + erff(a1*0.70710678118654752f));
    a2 = 0.5f*a2*(1.f + erff(a2*0.70710678118654752f));
    a3 = 0.5f*a3*(1.f + erff(a3*0.70710678118654752f));
    uint2 o;
    o.x = pk2(a0, a1);
    o.y = pk2(a2, a3);
    ((uint2*)(out + (size_t)n * HID))[tid] = o;
}

// ---------------- region means ----------------------------------------------
__global__ void regmean() {
    int blk = blockIdx.x, d = threadIdx.x;
    int n0 = (blk >> 4) * LL + (blk & 15) * RS;
    float sq = 0.f, sk = 0.f;
    for (int i = 0; i < RS; i++) {
        const float* p = g_qkv + (size_t)(n0 + i) * QKVC + d;
        sq += p[0];
        sk += p[DIM];
    }
    g_qr[blk*DIM + d] = sq * (1.f/RS);
    g_kr[blk*DIM + d] = sk * (1.f/RS);
}

// ---------------- region affinity + top-k -----------------------------------
__global__ void afftopk() {
    __shared__ float qs[16][257];
    __shared__ float ks[16][257];
    __shared__ float aff[16][17];
    int tb = blockIdx.x, tid = threadIdx.x;
    for (int idx = tid; idx < 16*256; idx += 256) {
        int rr = idx >> 8, d = idx & 255;
        qs[rr][d] = g_qr[(tb*16 + rr)*DIM + d];
        ks[rr][d] = g_kr[(tb*16 + rr)*DIM + d];
    }
    __syncthreads();
    int r = tid >> 4, s = tid & 15;
    float a = 0.f;
    #pragma unroll 8
    for (int d = 0; d < 256; d++) a += qs[r][d] * ks[s][d];
    aff[r][s] = a;
    __syncthreads();
    if (tid < 16) {
        float vals[16];
        #pragma unroll
        for (int s2 = 0; s2 < 16; s2++) vals[s2] = aff[tid][s2];
        #pragma unroll
        for (int m = 0; m < NTOPK; m++) {
            int best = 0; float bv = vals[0];
            #pragma unroll
            for (int s2 = 1; s2 < 16; s2++)
                if (vals[s2] > bv) { bv = vals[s2]; best = s2; }
            g_idx[(tb*16 + tid)*NTOPK + m] = best;
            vals[best] = -1e30f;
        }
    }
}

// ---------------- bf16 mma --------------------------------------------------
__device__ __forceinline__ void mma_bf16(float* d, const uint32_t* a, const uint32_t* b) {
    asm volatile(
        "mma.sync.aligned.m16n8k16.row.col.f32.bf16.bf16.f32 "
        "{%0,%1,%2,%3}, {%4,%5,%6,%7}, {%8,%9}, {%0,%1,%2,%3};\n"
        : "+f"(d[0]), "+f"(d[1]), "+f"(d[2]), "+f"(d[3])
        : "r"(a[0]), "r"(a[1]), "r"(a[2]), "r"(a[3]), "r"(b[0]), "r"(b[1]));
}

__device__ __forceinline__ float fexp_sc(float s) {
    const float C = 0.17677669529663687f * 1.4426950408889634f;
    float y = s * C;
    float z = y + 12582912.f;
    float n = z - 12582912.f;
    float f = y - n;
    float p = 0.0013333558f;
    p = fmaf(p, f, 0.0096181291f);
    p = fmaf(p, f, 0.0555041087f);
    p = fmaf(p, f, 0.2402265069f);
    p = fmaf(p, f, 0.6931471806f);
    p = fmaf(p, f, 1.0f);
    return __int_as_float(__float_as_int(p) + (__float_as_int(z) << 23));
}

// ---------------- bi-level attention (tensor cores, bf16 out) ---------------
__global__ void attn_mma() {
    int bid = blockIdx.x;
    int h  = bid & 7;
    int r  = (bid >> 3) & 15;
    int tb = bid >> 7;
    int t = threadIdx.x, lane = t & 31, w = t >> 5;

    __shared__ __nv_bfloat16 Ks[64*40];
    __shared__ __nv_bfloat16 Vt[32*72];

    int rlo  = lane >> 2;
    int qcol = (lane & 3) * 2;

    uint32_t qf[2][2][4];
    int qr_base = tb * LL + r * RS + w * 32;
    #pragma unroll
    for (int mt = 0; mt < 2; mt++) {
        #pragma unroll
        for (int kt = 0; kt < 2; kt++) {
            const float* qp = g_qkv + (size_t)(qr_base + mt*16 + rlo) * QKVC + h*HD + kt*16 + qcol;
            float2 v0 = *(const float2*)(qp);
            float2 v1 = *(const float2*)(qp + 8*QKVC);
            float2 v2 = *(const float2*)(qp + 8);
            float2 v3 = *(const float2*)(qp + 8*QKVC + 8);
            qf[mt][kt][0] = pk2(v0.x, v0.y);
            qf[mt][kt][1] = pk2(v1.x, v1.y);
            qf[mt][kt][2] = pk2(v2.x, v2.y);
            qf[mt][kt][3] = pk2(v3.x, v3.y);
        }
    }

    float oacc[2][4][4];
    #pragma unroll
    for (int mt = 0; mt < 2; mt++)
        #pragma unroll
        for (int nt = 0; nt < 4; nt++)
            #pragma unroll
            for (int q = 0; q < 4; q++) oacc[mt][nt][q] = 0.f;
    float rs[2][2] = {{0.f,0.f},{0.f,0.f}};

    for (int reg = 0; reg < NTOPK; reg++) {
        int s = g_idx[(tb*RR + r)*NTOPK + reg];
        int kvbase = tb * LL + s * RS;
        #pragma unroll
        for (int i = 0; i < 16; i++) {
            int flat = i*64 + t;
            int j  = flat >> 4;
            int d2 = (flat & 15) * 2;
            const float* kp = g_qkv + (size_t)(kvbase + j)*QKVC + DIM + h*HD + d2;
            float2 kv = *(const float2*)kp;
            float2 vv = *(const float2*)(kp + DIM);
            *(uint32_t*)&Ks[j*40 + d2] = pk2(kv.x, kv.y);
            Vt[d2*72 + j]     = __float2bfloat16(vv.x);
            Vt[(d2+1)*72 + j] = __float2bfloat16(vv.y);
        }
        __syncthreads();

        float sacc[2][8][4];
        #pragma unroll
        for (int mt = 0; mt < 2; mt++)
            #pragma unroll
            for (int nt = 0; nt < 8; nt++)
                #pragma unroll
                for (int q = 0; q < 4; q++) sacc[mt][nt][q] = 0.f;

        #pragma unroll
        for (int kt = 0; kt < 2; kt++) {
            #pragma unroll
            for (int nt = 0; nt < 8; nt++) {
                int j = nt*8 + rlo;
                int a0 = j*40 + kt*16 + qcol;
                uint32_t b0 = *(uint32_t*)&Ks[a0];
                uint32_t b1 = *(uint32_t*)&Ks[a0 + 8];
                uint32_t bfr[2] = {b0, b1};
                mma_bf16(sacc[0][nt], qf[0][kt], bfr);
                mma_bf16(sacc[1][nt], qf[1][kt], bfr);
            }
        }

        uint32_t pf[2][4][4];
        #pragma unroll
        for (int mt = 0; mt < 2; mt++) {
            #pragma unroll
            for (int nt = 0; nt < 8; nt++) {
                float e0 = fexp_sc(sacc[mt][nt][0]);
                float e1 = fexp_sc(sacc[mt][nt][1]);
                float e2 = fexp_sc(sacc[mt][nt][2]);
                float e3 = fexp_sc(sacc[mt][nt][3]);
                rs[mt][0] += e0 + e1;
                rs[mt][1] += e2 + e3;
                int kt2 = nt >> 1;
                if ((nt & 1) == 0) {
                    pf[mt][kt2][0] = pk2(e0, e1);
                    pf[mt][kt2][1] = pk2(e2, e3);
                } else {
                    pf[mt][kt2][2] = pk2(e0, e1);
                    pf[mt][kt2][3] = pk2(e2, e3);
                }
            }
        }

        #pragma unroll
        for (int kt2 = 0; kt2 < 4; kt2++) {
            #pragma unroll
            for (int nv = 0; nv < 4; nv++) {
                int d = nv*8 + rlo;
                int j0 = kt2*16 + qcol;
                uint32_t b0 = *(uint32_t*)&Vt[d*72 + j0];
                uint32_t b1 = *(uint32_t*)&Vt[d*72 + j0 + 8];
                uint32_t bfr[2] = {b0, b1};
                mma_bf16(oacc[0][nv], pf[0][kt2], bfr);
                mma_bf16(oacc[1][nv], pf[1][kt2], bfr);
            }
        }
        __syncthreads();
    }

    #pragma unroll
    for (int mt = 0; mt < 2; mt++)
        #pragma unroll
        for (int i = 0; i < 2; i++) {
            float v = rs[mt][i];
            v += __shfl_xor_sync(0xffffffffu, v, 1);
            v += __shfl_xor_sync(0xffffffffu, v, 2);
            rs[mt][i] = 1.f / v;
        }

    #pragma unroll
    for (int mt = 0; mt < 2; mt++) {
        int row0 = qr_base + mt*16 + rlo;
        #pragma unroll
        for (int nv = 0; nv < 4; nv++) {
            int d = h*HD + nv*8 + qcol;
            *(uint32_t*)(g_attn + (size_t)row0*DIM + d) =
                pk2(oacc[mt][nv][0]*rs[mt][0], oacc[mt][nv][1]*rs[mt][0]);
            *(uint32_t*)(g_attn + (size_t)(row0+8)*DIM + d) =
                pk2(oacc[mt][nv][2]*rs[mt][1], oacc[mt][nv][3]*rs[mt][1]);
        }
    }
}

// ---------------- bf16 tensor-core GEMM with residual epilogue --------------
// out[M,256] = res + scale * (A_bf16[M,K] @ B_f32[K,256] + bias)
__global__ void gemm_bf16_res(const __nv_bfloat16* __restrict__ A,
                              const float* __restrict__ B,
                              const float* __restrict__ bias,
                              const float* __restrict__ res,
                              const float* __restrict__ scale_p,
                              float* __restrict__ out,
                              int K) {
    __shared__ __align__(16) __nv_bfloat16 As[128*40];   // row stride 40 halves = 80B
    __shared__ __align__(16) __nv_bfloat16 Bs[32*136];   // row stride 136 halves = 272B
    int t = threadIdx.x;
    int lane = t & 31, warp = t >> 5;
    int wm = warp & 3;
    int wn = warp >> 2;
    int row0 = blockIdx.y * 128, col0 = blockIdx.x * 128;

    float acc[2][8][4];
    #pragma unroll
    for (int mt = 0; mt < 2; mt++)
        #pragma unroll
        for (int nt = 0; nt < 8; nt++)
            #pragma unroll
            for (int q = 0; q < 4; q++) acc[mt][nt][q] = 0.f;

    const __nv_bfloat16* Ag = A + (size_t)row0 * K;
    const float* Bg = B + col0;

    uint4  pa[2];
    float4 pb[4];
    // preload k-tile 0: A tile 128x32 bf16 (8KB) -> 2 x 256thr x uint4
    #pragma unroll
    for (int i = 0; i < 2; i++) {
        int flat = i*256 + t;                 // 0..511
        pa[i] = *(const uint4*)(Ag + (size_t)(flat >> 2)*K + (flat & 3)*8);
    }
    #pragma unroll
    for (int i = 0; i < 4; i++) {
        int flat = i*256 + t;                 // 0..1023
        pb[i] = *(const float4*)(Bg + (size_t)(flat >> 5)*256 + (flat & 31)*4);
    }
    #pragma unroll
    for (int i = 0; i < 2; i++) {
        int flat = i*256 + t;
        int ar = flat >> 2, j = flat & 3;
        *(uint4*)((uint32_t*)As + ar*20 + j*4) = pa[i];
    }
    #pragma unroll
    for (int i = 0; i < 4; i++) {
        int flat = i*256 + t;
        int bk = flat >> 5, bc4 = flat & 31;
        uint2 o; o.x = pk2(pb[i].x, pb[i].y); o.y = pk2(pb[i].z, pb[i].w);
        *(uint2*)((uint32_t*)Bs + bk*68 + bc4*2) = o;
    }
    __syncthreads();

    int nkt = K >> 5;
    for (int kt = 1; kt <= nkt; kt++) {
        if (kt < nkt) {
            int k0 = kt * 32;
            #pragma unroll
            for (int i = 0; i < 2; i++) {
                int flat = i*256 + t;
                pa[i] = *(const uint4*)(Ag + (size_t)(flat >> 2)*K + k0 + (flat & 3)*8);
            }
            #pragma unroll
            for (int i = 0; i < 4; i++) {
                int flat = i*256 + t;
                pb[i] = *(const float4*)(Bg + (size_t)(k0 + (flat >> 5))*256 + (flat & 31)*4);
            }
        }
        // compute on current tile
        #pragma unroll
        for (int ks = 0; ks < 2; ks++) {
            uint32_t af[2][4];
            #pragma unroll
            for (int mt = 0; mt < 2; mt++) {
                const __nv_bfloat16* ap = As + (wm*32 + mt*16 + (lane & 15))*40
                                             + ks*16 + ((lane >> 4) & 1)*8;
                uint32_t addr = smem_u32(ap);
                asm volatile("ldmatrix.sync.aligned.m8n8.x4.shared.b16 {%0,%1,%2,%3}, [%4];"
                    : "=r"(af[mt][0]), "=r"(af[mt][1]), "=r"(af[mt][2]), "=r"(af[mt][3])
                    : "r"(addr));
            }
            #pragma unroll
            for (int ng = 0; ng < 4; ng++) {
                const __nv_bfloat16* bp = Bs + (ks*16 + (lane & 7) + ((lane >> 3) & 1)*8)*136
                                             + wn*64 + ng*16 + ((lane >> 4) & 1)*8;
                uint32_t addr = smem_u32(bp);
                uint32_t bf4[4];
                asm volatile("ldmatrix.sync.aligned.m8n8.x4.trans.shared.b16 {%0,%1,%2,%3}, [%4];"
                    : "=r"(bf4[0]), "=r"(bf4[1]), "=r"(bf4[2]), "=r"(bf4[3])
                    : "r"(addr));
                mma_bf16(acc[0][2*ng],   af[0], &bf4[0]);
                mma_bf16(acc[0][2*ng+1], af[0], &bf4[2]);
                mma_bf16(acc[1][2*ng],   af[1], &bf4[0]);
                mma_bf16(acc[1][2*ng+1], af[1], &bf4[2]);
            }
        }
        __syncthreads();
        if (kt < nkt) {
            #pragma unroll
            for (int i = 0; i < 2; i++) {
                int flat = i*256 + t;
                int ar = flat >> 2, j = flat & 3;
                *(uint4*)((uint32_t*)As + ar*20 + j*4) = pa[i];
            }
            #pragma unroll
            for (int i = 0; i < 4; i++) {
                int flat = i*256 + t;
                int bk = flat >> 5, bc4 = flat & 31;
                uint2 o; o.x = pk2(pb[i].x, pb[i].y); o.y = pk2(pb[i].z, pb[i].w);
                *(uint2*)((uint32_t*)Bs + bk*68 + bc4*2) = o;
            }
            __syncthreads();
        }
    }

    float sc = *scale_p;
    int c = lane & 3, p = lane >> 2;
    #pragma unroll
    for (int mt = 0; mt < 2; mt++) {
        int r = row0 + wm*32 + mt*16 + p;
        #pragma unroll
        for (int nt = 0; nt < 8; nt++) {
            int cc = col0 + wn*64 + nt*8 + 2*c;
            float b0v = bias[cc], b1v = bias[cc + 1];
            size_t o1 = (size_t)r*256 + cc;
            float2 r1 = *(const float2*)(res + o1);
            float2 w1;
            w1.x = r1.x + sc*(acc[mt][nt][0] + b0v);
            w1.y = r1.y + sc*(acc[mt][nt][1] + b1v);
            *(float2*)(out + o1) = w1;
            size_t o2 = o1 + 8*256;
            float2 r2 = *(const float2*)(res + o2);
            float2 w2;
            w2.x = r2.x + sc*(acc[mt][nt][2] + b0v);
            w2.y = r2.y + sc*(acc[mt][nt][3] + b1v);
            *(float2*)(out + o2) = w2;
        }
    }
}

// ---------------- launch -----------------------------------------------------
extern "C" void kernel_launch(void* const* d_in, const int* in_sizes, int n_in,
                              void* d_out, int out_size) {
    const float* x     = (const float*)d_in[0];
    const float* bn1_g = (const float*)d_in[1];
    const float* bn1_b = (const float*)d_in[2];
    const float* Wqkv  = (const float*)d_in[3];
    const float* bqkv  = (const float*)d_in[4];
    const float* Wo    = (const float*)d_in[5];
    const float* bo    = (const float*)d_in[6];
    const float* bn2_g = (const float*)d_in[7];
    const float* bn2_b = (const float*)d_in[8];
    const float* W1    = (const float*)d_in[9];
    const float* b1    = (const float*)d_in[10];
    const float* W2    = (const float*)d_in[11];
    const float* b2    = (const float*)d_in[12];
    const float* scale = (const float*)d_in[13];
    float* out = (float*)d_out;

    float *p_x1, *p_qkv;
    __nv_bfloat16 *p_attn, *p_h, *p_w1bf;
    cudaGetSymbolAddress((void**)&p_x1,   g_x1);
    cudaGetSymbolAddress((void**)&p_attn, g_attn);
    cudaGetSymbolAddress((void**)&p_h,    g_h);
    cudaGetSymbolAddress((void**)&p_qkv,  g_qkv);
    cudaGetSymbolAddress((void**)&p_w1bf, g_w1bf);

    // convert W1 -> bf16 (per-launch, deterministic)
    cvtW<<<(DIM*HID/4)/256, 256>>>(W1, p_w1bf);

    // stage 1: bn1 + LIF -> s1
    stats1<<<128, 256>>>(x);
    stats2<<<1, 256>>>();
    bnlif<<<(BB*LL*DIM)/256, 256>>>(x, bn1_g, bn1_b);

    // qkv = s1 @ Wqkv + bqkv (fp32, protects top-k)
    spgemm_qkv<<<NROWS, 256>>>(Wqkv, bqkv, p_qkv);

    // region means, affinity, top-k, attention
    regmean<<<512, 256>>>();
    afftopk<<<32, 256>>>();
    attn_mma<<<LT*BB*RR*HEADS, 64>>>();

    // x1 = x + scale * (attn @ Wo + bo)
    dim3 gg(2, NROWS/128);
    gemm_bf16_res<<<gg, 256>>>(p_attn, Wo, bo, x, scale, p_x1, DIM);

    // stage 2: bn2 + LIF -> s2
    stats1<<<128, 256>>>(p_x1);
    stats2<<<1, 256>>>();
    bnlif<<<(BB*LL*DIM)/256, 256>>>(p_x1, bn2_g, bn2_b);

    // h = gelu(s2 @ W1 + b1)  (bf16 weights + bf16 out)
    spgemm_mlp<<<NROWS, 256>>>(b1, p_h);

    // out = x1 + scale * (h @ W2 + b2)
    gemm_bf16_res<<<gg, 256>>>(p_h, W2, b2, p_x1, scale, out, HID);
}